// round 11
// baseline (speedup 1.0000x reference)
#include <cuda_runtime.h>
#include <cuda_bf16.h>
#include <math.h>
#include <cstdint>

// Problem dims
#define Bv 128
#define Tv 1024
#define Iv 512
#define Hv 1024
#define Ov 256

#define NBLK_SCAN 128   // 16 k-chunks x 8 n-tiles
#define KCHUNKS   16

typedef unsigned long long ull;

// -------- scratch (device globals: no allocation allowed) --------
__device__ __nv_bfloat16 g_xh[(size_t)Tv * Bv * Iv]; // x split hi, [t][b][i]
__device__ __nv_bfloat16 g_xl[(size_t)Tv * Bv * Iv]; // x split lo, [t][b][i]
__device__ __nv_bfloat16 g_hh[Bv * Hv];              // hidden state, bf16 hi
__device__ __nv_bfloat16 g_hl[Bv * Hv];              // hidden state, bf16 lo
__device__ float g_part[KCHUNKS][Bv * Hv];           // split-K partials (8 MB)
__device__ unsigned g_bar_count;                     // monotonic arrivals
__device__ unsigned g_gen;                           // monotonic releases

// -------- barrier primitives (tid0-only; caller wraps with __syncthreads) ----
__device__ __forceinline__ void bar_arrive_flat() {
    // cumulative fence: CTA's prior stores (observed by tid0 via syncthreads)
    // become gpu-visible before our arrival is observed
    asm volatile("fence.acq_rel.gpu;" ::: "memory");
    unsigned prev;
    asm volatile("atom.relaxed.gpu.global.add.u32 %0, [%1], 1;"
                 : "=r"(prev) : "l"(&g_bar_count) : "memory");
    if ((prev & 127u) == 127u) {        // last of this instance (monotonic)
        asm volatile("fence.acq_rel.gpu;" ::: "memory");
        unsigned g;
        asm volatile("ld.relaxed.gpu.u32 %0, [%1];" : "=r"(g) : "l"(&g_gen));
        asm volatile("st.release.gpu.u32 [%0], %1;"
                     :: "l"(&g_gen), "r"(g + 1) : "memory");
    }
}
__device__ __forceinline__ void bar_wait(unsigned gen0, unsigned n) {
    unsigned cur;
    do {
        asm volatile("ld.acquire.gpu.u32 %0, [%1];"
                     : "=r"(cur) : "l"(&g_gen) : "memory");
    } while ((cur - gen0) < n);
}

// -------- mma.sync / ldmatrix helpers --------
__device__ __forceinline__ uint32_t smem_u32(const void* p) {
    uint32_t a;
    asm("{ .reg .u64 t; cvta.to.shared.u64 t, %1; cvt.u32.u64 %0, t; }"
        : "=r"(a) : "l"(p));
    return a;
}
__device__ __forceinline__ void ldsm4(uint32_t r[4], uint32_t addr) {
    asm volatile("ldmatrix.sync.aligned.m8n8.x4.shared.b16 {%0,%1,%2,%3}, [%4];"
                 : "=r"(r[0]), "=r"(r[1]), "=r"(r[2]), "=r"(r[3]) : "r"(addr));
}
__device__ __forceinline__ void mma_bf16(float d[4], const uint32_t a[4],
                                         const uint32_t b0, const uint32_t b1) {
    asm volatile(
        "mma.sync.aligned.m16n8k16.row.col.f32.bf16.bf16.f32 "
        "{%0,%1,%2,%3}, {%4,%5,%6,%7}, {%8,%9}, {%0,%1,%2,%3};"
        : "+f"(d[0]), "+f"(d[1]), "+f"(d[2]), "+f"(d[3])
        : "r"(a[0]), "r"(a[1]), "r"(a[2]), "r"(a[3]), "r"(b0), "r"(b1));
}

__device__ __forceinline__ uint32_t bf16pack(float a, float b) {
    __nv_bfloat16 x = __float2bfloat16(a);
    __nv_bfloat16 y = __float2bfloat16(b);
    return (uint32_t)__bfloat16_as_ushort(x) |
           ((uint32_t)__bfloat16_as_ushort(y) << 16);
}

// ============================================================
// Kernel 0: split x into bf16 hi/lo, transpose [b][t][i] -> [t][b][i]
// ============================================================
__global__ void __launch_bounds__(256) split_x(const float* __restrict__ X)
{
    size_t idx8 = (size_t)blockIdx.x * 256 + threadIdx.x;  // over B*T*I/8
    if (idx8 >= (size_t)Bv * Tv * Iv / 8) return;
    int i = (int)(idx8 & 63) * 8;
    int t = (int)((idx8 >> 6) & 1023);
    int b = (int)(idx8 >> 16);

    const float* src = X + (((size_t)b * Tv + t) * Iv + i);
    float4 f0 = *(const float4*)(src + 0);
    float4 f1 = *(const float4*)(src + 4);
    float f[8] = {f0.x, f0.y, f0.z, f0.w, f1.x, f1.y, f1.z, f1.w};

    uint32_t hi[4], lo[4];
#pragma unroll
    for (int j = 0; j < 4; j++) {
        __nv_bfloat16 h0 = __float2bfloat16(f[2 * j]);
        __nv_bfloat16 h1 = __float2bfloat16(f[2 * j + 1]);
        hi[j] = (uint32_t)__bfloat16_as_ushort(h0) |
                ((uint32_t)__bfloat16_as_ushort(h1) << 16);
        lo[j] = bf16pack(f[2 * j] - __bfloat162float(h0),
                         f[2 * j + 1] - __bfloat162float(h1));
    }
    size_t o = (((size_t)t * Bv + b) * Iv + i);
    *(uint4*)&g_xh[o] = *(const uint4*)hi;
    *(uint4*)&g_xl[o] = *(const uint4*)lo;
}

// ============================================================
// Kernel B: persistent fused scan (R9/R10-proven compute core).
// Barrier: flat monotonic counter, tid0-only cumulative fence,
// early arrival with x[t+1] staging inside the wait shadow.
// ============================================================
__global__ void __launch_bounds__(256, 1) scan_kernel(
    const float* __restrict__ WR, const float* __restrict__ WK,
    const float* __restrict__ bias)
{
    extern __shared__ __align__(1024) char smem[];
    char* sAhh = smem;
    char* sAhl = smem + 16384;
    char* sBwh = smem + 32768;
    char* sBwl = smem + 49152;
    char* sXhh = smem + 65536;
    char* sXhl = smem + 81920;
    char* sKwh = smem + 98304;
    char* sKwl = smem + 114688;
    const uint32_t pAhh = smem_u32(smem);
    const uint32_t pAhl = pAhh + 16384;
    const uint32_t pBwh = pAhh + 32768;
    const uint32_t pBwl = pAhh + 49152;
    const uint32_t pXhh = pAhh + 65536;
    const uint32_t pXhl = pAhh + 81920;
    const uint32_t pKwh = pAhh + 98304;
    const uint32_t pKwl = pAhh + 114688;

    const int tid = threadIdx.x;
    const int wid = tid >> 5;
    const int lid = tid & 31;
    const int bi = blockIdx.x;
    const int kc = bi >> 3;
    const int nt = bi & 7;
    const int kbase = kc * 64;
    const int xbase = kc * 32;
    const int nbase = nt * 128;
    const int e = (bi * 256 + tid) * 4;

    const int wm = wid & 1;
    const int wn = wid >> 1;

    const int rowA = ((lid >> 3) & 1) * 8 + (lid & 7);
    const int khA  = (lid >> 4) * 16;
    const int rowB = ((lid >> 4) & 1) * 8 + (lid & 7);
    const int khB  = ((lid >> 3) & 1) * 16;
    const int sw   = (lid & 7) << 4;
    const uint32_t aHiBase = pAhh + (wm * 64 + rowA) * 128;
    const uint32_t aLoBase = pAhl + (wm * 64 + rowA) * 128;
    const uint32_t bHiBase = pBwh + (wn * 32 + rowB) * 128;
    const uint32_t bLoBase = pBwl + (wn * 32 + rowB) * 128;
    const uint32_t xHiBase = pXhh + (wm * 64 + rowA) * 128;
    const uint32_t xLoBase = pXhl + (wm * 64 + rowA) * 128;
    const uint32_t kHiBase = pKwh + (wn * 32 + rowB) * 128;
    const uint32_t kLoBase = pKwl + (wn * 32 + rowB) * 128;

    // barrier baseline (before our first arrival; safe: release #1 needs all)
    unsigned gen0 = 0;
    if (tid == 0) {
        asm volatile("ld.relaxed.gpu.u32 %0, [%1];" : "=r"(gen0) : "l"(&g_gen));
    }
    unsigned bcnt = 0;   // barrier instance counter (tid0 meaningful)

    // ---- preload Wr slice (split hi/lo, [n][k], swizzled) ----
    for (int idx = tid; idx < 128 * 64; idx += 256) {
        int n = idx & 127;
        int k = idx >> 7;
        float w = WR[(size_t)(kbase + k) * Hv + nbase + n];
        __nv_bfloat16 wh = __float2bfloat16(w);
        __nv_bfloat16 wl = __float2bfloat16(w - __bfloat162float(wh));
        uint32_t off = n * 128 + ((k * 2) ^ ((n & 7) << 4));
        *(__nv_bfloat16*)(sBwh + off) = wh;
        *(__nv_bfloat16*)(sBwl + off) = wl;
    }
    // ---- preload Wk slice ----
    for (int idx = tid; idx < 128 * 32; idx += 256) {
        int n = idx & 127;
        int k = idx >> 7;
        float w = WK[(size_t)(xbase + k) * Hv + nbase + n];
        __nv_bfloat16 wh = __float2bfloat16(w);
        __nv_bfloat16 wl = __float2bfloat16(w - __bfloat162float(wh));
        uint32_t off = n * 128 + ((k * 2) ^ ((n & 7) << 4));
        *(__nv_bfloat16*)(sKwh + off) = wh;
        *(__nv_bfloat16*)(sKwl + off) = wl;
    }

    *(ull*)&g_hh[e] = 0ull;
    *(ull*)&g_hl[e] = 0ull;

    float4 bb = *(const float4*)&bias[tid * 4];

    const int srow = tid >> 1;
    const int soff = (tid & 1) * 64;
    const int xoff = (tid & 1) * 32;
    const uint32_t rb = srow * 128;
    const uint32_t sws = (srow & 7) << 4;

    // ---- stage x[0] tile ----
    {
        const char* xh = (const char*)(g_xh + (size_t)srow * Iv + xbase) + xoff;
        const char* xl = (const char*)(g_xl + (size_t)srow * Iv + xbase) + xoff;
        uint4 a0 = __ldcg((const uint4*)xh + 0);
        uint4 a1 = __ldcg((const uint4*)xh + 1);
        uint4 b0 = __ldcg((const uint4*)xl + 0);
        uint4 b1 = __ldcg((const uint4*)xl + 1);
        *(uint4*)(sXhh + rb + ((xoff +  0) ^ sws)) = a0;
        *(uint4*)(sXhh + rb + ((xoff + 16) ^ sws)) = a1;
        *(uint4*)(sXhl + rb + ((xoff +  0) ^ sws)) = b0;
        *(uint4*)(sXhl + rb + ((xoff + 16) ^ sws)) = b1;
    }

    // ---- initial barrier ----
    __syncthreads();
    if (tid == 0) { bcnt++; bar_arrive_flat(); bar_wait(gen0, bcnt); }
    __syncthreads();

#pragma unroll 1
    for (int t = 0; t < Tv; t++) {
        // ---- stage h slice (bf16 hi/lo, K-major, swizzled) ----
        {
            const char* sh = (const char*)(g_hh + (size_t)srow * Hv + kbase) + soff;
            const char* sl = (const char*)(g_hl + (size_t)srow * Hv + kbase) + soff;
            uint4 h0 = __ldcg((const uint4*)sh + 0);
            uint4 h1 = __ldcg((const uint4*)sh + 1);
            uint4 h2 = __ldcg((const uint4*)sh + 2);
            uint4 h3 = __ldcg((const uint4*)sh + 3);
            uint4 l0 = __ldcg((const uint4*)sl + 0);
            uint4 l1 = __ldcg((const uint4*)sl + 1);
            uint4 l2 = __ldcg((const uint4*)sl + 2);
            uint4 l3 = __ldcg((const uint4*)sl + 3);
            *(uint4*)(sAhh + rb + ((soff +  0) ^ sws)) = h0;
            *(uint4*)(sAhh + rb + ((soff + 16) ^ sws)) = h1;
            *(uint4*)(sAhh + rb + ((soff + 32) ^ sws)) = h2;
            *(uint4*)(sAhh + rb + ((soff + 48) ^ sws)) = h3;
            *(uint4*)(sAhl + rb + ((soff +  0) ^ sws)) = l0;
            *(uint4*)(sAhl + rb + ((soff + 16) ^ sws)) = l1;
            *(uint4*)(sAhl + rb + ((soff + 32) ^ sws)) = l2;
            *(uint4*)(sAhl + rb + ((soff + 48) ^ sws)) = l3;
        }
        __syncthreads();

        // ---- GEMM: rec (K=64) + xp (K=32), 3-term each ----
        float D[4][4][4];
#pragma unroll
        for (int i = 0; i < 4; i++)
#pragma unroll
            for (int j = 0; j < 4; j++)
#pragma unroll
                for (int q = 0; q < 4; q++) D[i][j][q] = 0.f;

#pragma unroll
        for (int ks = 0; ks < 4; ks++) {
            const uint32_t koffA = ((ks * 32) | khA) ^ sw;
            const uint32_t koffB = ((ks * 32) | khB) ^ sw;
            uint32_t Ah[4][4], Al[4][4], Bh[2][4], Bl[2][4];
#pragma unroll
            for (int mt = 0; mt < 4; mt++) {
                ldsm4(Ah[mt], aHiBase + mt * 2048 + koffA);
                ldsm4(Al[mt], aLoBase + mt * 2048 + koffA);
            }
#pragma unroll
            for (int np = 0; np < 2; np++) {
                ldsm4(Bh[np], bHiBase + np * 2048 + koffB);
                ldsm4(Bl[np], bLoBase + np * 2048 + koffB);
            }
#pragma unroll
            for (int mt = 0; mt < 4; mt++) {
#pragma unroll
                for (int ntl = 0; ntl < 4; ntl++) {
                    const int np = ntl >> 1, q = (ntl & 1) * 2;
                    mma_bf16(D[mt][ntl], Ah[mt], Bh[np][q], Bh[np][q + 1]);
                    mma_bf16(D[mt][ntl], Al[mt], Bh[np][q], Bh[np][q + 1]);
                    mma_bf16(D[mt][ntl], Ah[mt], Bl[np][q], Bl[np][q + 1]);
                }
            }
        }
#pragma unroll
        for (int ks = 0; ks < 2; ks++) {
            const uint32_t koffA = ((ks * 32) | khA) ^ sw;
            const uint32_t koffB = ((ks * 32) | khB) ^ sw;
            uint32_t Ah[4][4], Al[4][4], Bh[2][4], Bl[2][4];
#pragma unroll
            for (int mt = 0; mt < 4; mt++) {
                ldsm4(Ah[mt], xHiBase + mt * 2048 + koffA);
                ldsm4(Al[mt], xLoBase + mt * 2048 + koffA);
            }
#pragma unroll
            for (int np = 0; np < 2; np++) {
                ldsm4(Bh[np], kHiBase + np * 2048 + koffB);
                ldsm4(Bl[np], kLoBase + np * 2048 + koffB);
            }
#pragma unroll
            for (int mt = 0; mt < 4; mt++) {
#pragma unroll
                for (int ntl = 0; ntl < 4; ntl++) {
                    const int np = ntl >> 1, q = (ntl & 1) * 2;
                    mma_bf16(D[mt][ntl], Ah[mt], Bh[np][q], Bh[np][q + 1]);
                    mma_bf16(D[mt][ntl], Al[mt], Bh[np][q], Bh[np][q + 1]);
                    mma_bf16(D[mt][ntl], Ah[mt], Bl[np][q], Bl[np][q + 1]);
                }
            }
        }

        // ---- write split-K partials ----
        {
            const int g = lid >> 2, c2 = (lid & 3) * 2;
            float* P = g_part[kc];
#pragma unroll
            for (int mt = 0; mt < 4; mt++) {
#pragma unroll
                for (int ntl = 0; ntl < 4; ntl++) {
                    int row0 = wm * 64 + mt * 16 + g;
                    int col = nbase + wn * 32 + ntl * 8 + c2;
                    float2 v0 = {D[mt][ntl][0], D[mt][ntl][1]};
                    float2 v1 = {D[mt][ntl][2], D[mt][ntl][3]};
                    *(float2*)&P[(size_t)row0 * Hv + col] = v0;
                    *(float2*)&P[(size_t)(row0 + 8) * Hv + col] = v1;
                }
            }
        }

        // ---- barrier 1: early arrival, x[t+1] staging in the wait shadow ----
        __syncthreads();                 // partial stores done CTA-wide
        if (tid == 0) { bcnt++; bar_arrive_flat(); }
        if (t + 1 < Tv) {
            const char* xh = (const char*)(g_xh + ((size_t)(t + 1) * Bv + srow) * Iv + xbase) + xoff;
            const char* xl = (const char*)(g_xl + ((size_t)(t + 1) * Bv + srow) * Iv + xbase) + xoff;
            uint4 a0 = __ldcg((const uint4*)xh + 0);
            uint4 a1 = __ldcg((const uint4*)xh + 1);
            uint4 b0 = __ldcg((const uint4*)xl + 0);
            uint4 b1 = __ldcg((const uint4*)xl + 1);
            *(uint4*)(sXhh + rb + ((xoff +  0) ^ sws)) = a0;
            *(uint4*)(sXhh + rb + ((xoff + 16) ^ sws)) = a1;
            *(uint4*)(sXhl + rb + ((xoff +  0) ^ sws)) = b0;
            *(uint4*)(sXhl + rb + ((xoff + 16) ^ sws)) = b1;
        }
        if (tid == 0) bar_wait(gen0, bcnt);
        __syncthreads();

        // ---- phase 2: reduce partials + bias + tanh -> h (bf16 hi/lo) ----
        {
            float4 s = bb;
#pragma unroll
            for (int c = 0; c < KCHUNKS; c++) {
                float4 p = __ldcg((const float4*)&g_part[c][e]);
                s.x += p.x; s.y += p.y; s.z += p.z; s.w += p.w;
            }
            float h[4] = {tanhf(s.x), tanhf(s.y), tanhf(s.z), tanhf(s.w)};
            unsigned short hh[4], hl[4];
#pragma unroll
            for (int j = 0; j < 4; j++) {
                __nv_bfloat16 a = __float2bfloat16(h[j]);
                __nv_bfloat16 b = __float2bfloat16(h[j] - __bfloat162float(a));
                hh[j] = __bfloat16_as_ushort(a);
                hl[j] = __bfloat16_as_ushort(b);
            }
            *(ull*)&g_hh[e] = *(const ull*)hh;
            *(ull*)&g_hl[e] = *(const ull*)hl;
        }

        // ---- barrier 2 ----
        __syncthreads();
        if (tid == 0) { bcnt++; bar_arrive_flat(); bar_wait(gen0, bcnt); }
        __syncthreads();
    }
}

// ============================================================
// Kernel C: out[b][o] = h_last[b][:] @ fc_w[:, o] + fc_b[o]
// ============================================================
__global__ void __launch_bounds__(256, 1) fc_kernel(
    const float* __restrict__ fcw, const float* __restrict__ fcb,
    float* __restrict__ out)
{
    __shared__ float hs[Hv];
    const int b = blockIdx.x;
    for (int i = threadIdx.x; i < Hv; i += 256) {
        hs[i] = __bfloat162float(g_hh[(size_t)b * Hv + i]) +
                __bfloat162float(g_hl[(size_t)b * Hv + i]);
    }
    __syncthreads();

    const int o = threadIdx.x;
    float a0 = 0.f, a1 = 0.f, a2 = 0.f, a3 = 0.f;
#pragma unroll 4
    for (int k = 0; k < Hv; k += 4) {
        a0 = fmaf(hs[k + 0], fcw[(size_t)(k + 0) * Ov + o], a0);
        a1 = fmaf(hs[k + 1], fcw[(size_t)(k + 1) * Ov + o], a1);
        a2 = fmaf(hs[k + 2], fcw[(size_t)(k + 2) * Ov + o], a2);
        a3 = fmaf(hs[k + 3], fcw[(size_t)(k + 3) * Ov + o], a3);
    }
    out[(size_t)b * Ov + o] = (a0 + a1) + (a2 + a3) + fcb[o];
}

// ============================================================
extern "C" void kernel_launch(void* const* d_in, const int* in_sizes, int n_in,
                              void* d_out, int out_size)
{
    const float* x   = (const float*)d_in[0];
    const float* wk  = (const float*)d_in[1];
    const float* wr  = (const float*)d_in[2];
    const float* bs  = (const float*)d_in[3];
    const float* fcw = (const float*)d_in[4];
    const float* fcb = (const float*)d_in[5];
    float* out = (float*)d_out;

    static int smem_set = 0;
    if (!smem_set) {
        cudaFuncSetAttribute(scan_kernel,
                             cudaFuncAttributeMaxDynamicSharedMemorySize, 131072);
        smem_set = 1;
    }

    size_t nx8 = (size_t)Bv * Tv * Iv / 8;
    split_x<<<(unsigned)((nx8 + 255) / 256), 256>>>(x);
    scan_kernel<<<NBLK_SCAN, 256, 131072>>>(wr, wk, bs);
    fc_kernel<<<Bv, 256>>>(fcw, fcb, out);
}